// round 7
// baseline (speedup 1.0000x reference)
#include <cuda_runtime.h>
#include <math.h>

// ---------------- problem constants ----------------
#define NN 50000
#define EE 800000
#define HC 128          // HEADS * C_OUT
#define NSLOT (EE + NN) // edges + self loops
#define NEG_SLOPE 0.2f
#define BN_EPS 1e-5f
#define NB_SCAN ((NN + 255) / 256)   // 196
#define LOG2E 1.44269504088896f

// ---------------- device-global scratch (no allocs allowed) ----------------
__device__ int    g_is64;
__device__ int    g_deg[NN];
__device__ int    g_cursor[NN];
__device__ float  g_wsum[NN];
__device__ int    g_rowstart[NN + 1];
__device__ int    g_part[256];
__device__ int    g_csrc[NSLOT];
__device__ float  g_cw[NSLOT];
__device__ float  g_xl[NN * HC];
__device__ float  g_xr[NN * HC];
__device__ float  g_h1[NN * HC];    // raw GAT1 output
__device__ float  g_h1a[NN * HC];   // after BN + ELU
__device__ double g_bnsum[HC], g_bnsq[HC];

// ---------------- helpers ----------------
// edge_index may be int64 (reference dtype) or int32 (JAX x64-off downcast).
// int64 little-endian with values < 2^31 -> every odd 32-bit word is zero.
__device__ __forceinline__ void load_edge(const int* __restrict__ ei, int e, int E,
                                          int& s, int& d) {
    if (g_is64) { s = ei[2 * e]; d = ei[2 * (E + e)]; }
    else        { s = ei[e];     d = ei[E + e]; }
}

// zero scratch + detect int64-vs-int32 layout (fused; one launch)
__global__ void zero_detect_kernel(const int* __restrict__ ei) {
    int i = blockIdx.x * blockDim.x + threadIdx.x;
    if (i < NN) { g_deg[i] = 0; g_wsum[i] = 0.f; g_cursor[i] = 0; }
    if (i < HC) { g_bnsum[i] = 0.0; g_bnsq[i] = 0.0; }
    if (blockIdx.x == 0 && threadIdx.x == 0) {
        int z = 0;
        #pragma unroll
        for (int j = 1; j < 64; j += 2) z |= ei[j];
        g_is64 = (z == 0) ? 1 : 0;
    }
}

__global__ void deg_kernel(const int* __restrict__ ei, const float* __restrict__ ew, int E) {
    int e = blockIdx.x * blockDim.x + threadIdx.x;
    if (e >= E) return;
    int s, d; load_edge(ei, e, E, s, d);
    (void)s;
    atomicAdd(&g_deg[d], 1);
    atomicAdd(&g_wsum[d], ew[e]);
}

// -------- 3-kernel exclusive scan over counts = deg[i] + 1 --------
__global__ void scan_part(int n) {
    __shared__ int sm[256];
    int tid = threadIdx.x;
    int i = blockIdx.x * 256 + tid;
    int v = (i < n) ? (g_deg[i] + 1) : 0;
    sm[tid] = v; __syncthreads();
    for (int off = 128; off > 0; off >>= 1) {
        if (tid < off) sm[tid] += sm[tid + off];
        __syncthreads();
    }
    if (tid == 0) g_part[blockIdx.x] = sm[0];
}

__global__ void scan_mid(int nb, int total) {
    __shared__ int sm[256];
    int tid = threadIdx.x;
    int v = (tid < nb) ? g_part[tid] : 0;
    sm[tid] = v; __syncthreads();
    for (int off = 1; off < 256; off <<= 1) {
        int t = (tid >= off) ? sm[tid - off] : 0;
        __syncthreads();
        sm[tid] += t;
        __syncthreads();
    }
    if (tid < nb) g_part[tid] = sm[tid] - v;   // exclusive
    if (tid == 0) g_rowstart[NN] = total;
}

__global__ void scan_final(int n) {
    __shared__ int sm[256];
    int tid = threadIdx.x;
    int i = blockIdx.x * 256 + tid;
    int v = (i < n) ? (g_deg[i] + 1) : 0;
    sm[tid] = v; __syncthreads();
    for (int off = 1; off < 256; off <<= 1) {
        int t = (tid >= off) ? sm[tid - off] : 0;
        __syncthreads();
        sm[tid] += t;
        __syncthreads();
    }
    if (i < n) g_rowstart[i] = g_part[blockIdx.x] + sm[tid] - v;   // exclusive
}

__global__ void csr_fill(const int* __restrict__ ei, const float* __restrict__ ew, int E) {
    int e = blockIdx.x * blockDim.x + threadIdx.x;
    if (e >= E) return;
    int s, d; load_edge(ei, e, E, s, d);
    int pos = atomicAdd(&g_cursor[d], 1);
    int slot = g_rowstart[d] + pos;
    g_csrc[slot] = s;
    g_cw[slot]   = ew[e];
}

// self loop fill; loop weight = mean incoming weight (0 if no in-edges)
__global__ void self_fill(int n) {
    int i = blockIdx.x * blockDim.x + threadIdx.x;
    if (i >= n) return;
    int slot = g_rowstart[i + 1] - 1;  // last slot of node i's segment
    g_csrc[slot] = i;
    g_cw[slot]   = g_wsum[i] / fmaxf((float)g_deg[i], 1.f);
}

// -------- SGEMM: O[M,128] = A[M,128] @ W[128,128] + b, dual-W via gridDim.z --------
// BM=BN=128, BK=8, 8x8 microtiles, 256 threads, register-prefetch pipelined.
__global__ __launch_bounds__(256) void sgemm_dual(
    const float* __restrict__ Aext,
    const float* __restrict__ W0, const float* __restrict__ b0,
    const float* __restrict__ W1, const float* __restrict__ b1,
    int M, int useH1a)
{
    const float* __restrict__ A    = useH1a ? g_h1a : Aext;
    const float* __restrict__ W    = blockIdx.z ? W1 : W0;
    const float* __restrict__ bias = blockIdx.z ? b1 : b0;
    float* __restrict__ O          = blockIdx.z ? g_xr : g_xl;

    __shared__ float As[8][128];  // [k][row]
    __shared__ float Bs[8][128];  // [k][col]

    int tid = threadIdx.x;
    int row0 = blockIdx.x * 128;
    int ty = tid / 16, tx = tid % 16;

    int a_r = tid >> 1;            // 0..127
    int a_c = (tid & 1) * 4;       // 0 or 4
    int b_r = tid >> 5;            // 0..7
    int b_c = (tid & 31) * 4;      // 0..124
    bool a_ok = (row0 + a_r) < M;
    const float* Aptr = A + (size_t)(row0 + a_r) * HC + a_c;
    const float* Wptr = W + b_r * 128 + b_c;

    float acc[8][8];
    #pragma unroll
    for (int i = 0; i < 8; i++)
        #pragma unroll
        for (int j = 0; j < 8; j++) acc[i][j] = 0.f;

    // prologue loads for k0 = 0
    float4 av = a_ok ? *(const float4*)(Aptr) : make_float4(0.f, 0.f, 0.f, 0.f);
    float4 bv = *(const float4*)(Wptr);

    for (int k0 = 0; k0 < 128; k0 += 8) {
        __syncthreads();   // previous compute done reading smem
        As[a_c + 0][a_r] = av.x; As[a_c + 1][a_r] = av.y;
        As[a_c + 2][a_r] = av.z; As[a_c + 3][a_r] = av.w;
        *(float4*)&Bs[b_r][b_c] = bv;
        __syncthreads();
        if (k0 + 8 < 128) {   // prefetch next tile; latency hidden by FMAs below
            av = a_ok ? *(const float4*)(Aptr + k0 + 8) : make_float4(0.f, 0.f, 0.f, 0.f);
            bv = *(const float4*)(Wptr + (k0 + 8) * 128);
        }
        #pragma unroll
        for (int k = 0; k < 8; k++) {
            float ra[8], rb[8];
            #pragma unroll
            for (int i = 0; i < 8; i++) ra[i] = As[k][ty * 8 + i];
            #pragma unroll
            for (int j = 0; j < 8; j++) rb[j] = Bs[k][tx * 8 + j];
            #pragma unroll
            for (int i = 0; i < 8; i++)
                #pragma unroll
                for (int j = 0; j < 8; j++)
                    acc[i][j] = fmaf(ra[i], rb[j], acc[i][j]);
        }
    }

    #pragma unroll
    for (int i = 0; i < 8; i++) {
        int r = row0 + ty * 8 + i;
        if (r < M) {
            #pragma unroll
            for (int j = 0; j < 8; j++) acc[i][j] += __ldg(bias + tx * 8 + j);
            float4 v0 = make_float4(acc[i][0], acc[i][1], acc[i][2], acc[i][3]);
            float4 v1 = make_float4(acc[i][4], acc[i][5], acc[i][6], acc[i][7]);
            *(float4*)(O + (size_t)r * HC + tx * 8)     = v0;
            *(float4*)(O + (size_t)r * HC + tx * 8 + 4) = v1;
        }
    }
}

// -------- GATv2 aggregation: one warp per (node, head), lane = channel --------
// Online softmax (base 2, log2e folded into att). 2 nodes per block; edge loop
// processes 4 edges/iteration with 4 independent accumulator states (deep ILP:
// 4 overlapped shuffle-reduce chains, 4 batched gathers) merged analytically at
// the end. States that saw no edge contribute 0 via exp2(-inf)=0; every node
// has >=1 edge (self loop) so the merged max is finite.
__global__ __launch_bounds__(256) void gat_agg(
    const float* __restrict__ We, const float* __restrict__ att,
    const float* __restrict__ bias,
    const float* __restrict__ emb, float* __restrict__ outFinal,
    int mode, int n)
{
    int node = blockIdx.x * 2 + (threadIdx.x >> 7);
    if (node >= n) return;
    int col = threadIdx.x & 127;           // channel

    float att_v = __ldg(att + col) * LOG2E;   // base-2 softmax
    float we_v  = __ldg(We + col);
    float xr_v  = g_xr[(size_t)node * HC + col];
    int start = g_rowstart[node], end = g_rowstart[node + 1];

    float m[4], s[4], a[4];
    #pragma unroll
    for (int j = 0; j < 4; j++) { m[j] = -INFINITY; s[j] = 0.f; a[j] = 0.f; }

    int i = start;
    if (i + 4 <= end) {
        // prefetched indices/weights for the current quad
        int   src[4]; float w[4];
        #pragma unroll
        for (int j = 0; j < 4; j++) { src[j] = __ldg(&g_csrc[i + j]); w[j] = __ldg(&g_cw[i + j]); }
        for (; i + 4 <= end; ) {
            float x[4];
            #pragma unroll
            for (int j = 0; j < 4; j++) x[j] = __ldg(g_xl + (size_t)src[j] * HC + col);
            float cw[4];
            #pragma unroll
            for (int j = 0; j < 4; j++) cw[j] = w[j];
            i += 4;
            if (i + 4 <= end) {     // prefetch next quad's indices/weights
                #pragma unroll
                for (int j = 0; j < 4; j++) { src[j] = __ldg(&g_csrc[i + j]); w[j] = __ldg(&g_cw[i + j]); }
            }
            float l[4];
            #pragma unroll
            for (int j = 0; j < 4; j++) {
                float t = fmaf(cw[j], we_v, x[j] + xr_v);
                t = fmaxf(t, NEG_SLOPE * t);
                l[j] = att_v * t;
            }
            #pragma unroll
            for (int o = 16; o; o >>= 1) {
                #pragma unroll
                for (int j = 0; j < 4; j++) l[j] += __shfl_xor_sync(0xffffffffu, l[j], o);
            }
            #pragma unroll
            for (int j = 0; j < 4; j++) {
                float nm = fmaxf(m[j], l[j]);
                float p  = exp2f(l[j] - nm);
                float sc = exp2f(m[j] - nm);
                s[j] = fmaf(s[j], sc, p);
                a[j] = fmaf(a[j], sc, p * x[j]);
                m[j] = nm;
            }
        }
    }
    for (; i < end; ++i) {  // tail (0..3 edges), folded into state 0
        int   srcT = __ldg(&g_csrc[i]);
        float wT   = __ldg(&g_cw[i]);
        float x0 = __ldg(g_xl + (size_t)srcT * HC + col);
        float t0 = fmaf(wT, we_v, x0 + xr_v); t0 = fmaxf(t0, NEG_SLOPE * t0);
        float l0 = att_v * t0;
        #pragma unroll
        for (int o = 16; o; o >>= 1) l0 += __shfl_xor_sync(0xffffffffu, l0, o);
        float nm = fmaxf(m[0], l0);
        float p  = exp2f(l0 - nm);
        float sc = exp2f(m[0] - nm);
        s[0] = fmaf(s[0], sc, p);
        a[0] = fmaf(a[0], sc, p * x0);
        m[0] = nm;
    }
    // merge the four online states
    float mm = fmaxf(fmaxf(m[0], m[1]), fmaxf(m[2], m[3]));
    float ssum = 0.f, asum = 0.f;
    #pragma unroll
    for (int j = 0; j < 4; j++) {
        float c = exp2f(m[j] - mm);   // 0 for untouched states (m=-inf)
        ssum = fmaf(s[j], c, ssum);
        asum = fmaf(a[j], c, asum);
    }

    float v = asum / ssum + __ldg(bias + col);
    size_t idx = (size_t)node * HC + col;
    if (mode) {
        outFinal[idx] = (emb[idx] + g_h1a[idx] + v) * (1.f / 3.f);
    } else {
        g_h1[idx] = v;
    }
}

// -------- BatchNorm (training-style stats) + ELU --------
__global__ __launch_bounds__(128) void bn_stats(int n) {
    int c = threadIdx.x;
    float s = 0.f, q = 0.f;
    for (int r = blockIdx.x; r < n; r += gridDim.x) {
        float v = g_h1[(size_t)r * HC + c];
        s += v; q += v * v;
    }
    atomicAdd(&g_bnsum[c], (double)s);
    atomicAdd(&g_bnsq[c], (double)q);
}

// mu/inv computed inline from the double sums (no separate bn_fin launch).
// float4 path: 4 consecutive channels per thread.
__global__ void bn_apply(const float* __restrict__ gamma, const float* __restrict__ beta, int n) {
    int idx4 = blockIdx.x * blockDim.x + threadIdx.x;     // vec4 index
    if (idx4 >= n * (HC / 4)) return;
    int c4 = (idx4 & (HC / 4 - 1)) * 4;                   // first channel of group
    double inv_n = 1.0 / n;
    float4 v = *(const float4*)&g_h1[(size_t)idx4 * 4];
    float r[4] = {v.x, v.y, v.z, v.w};
    #pragma unroll
    for (int j = 0; j < 4; j++) {
        int c = c4 + j;
        double mu = g_bnsum[c] * inv_n;
        double var = g_bnsq[c] * inv_n - mu * mu;
        float inv = rsqrtf((float)var + BN_EPS);
        float t = fmaf(__ldg(gamma + c) * (r[j] - (float)mu), inv, __ldg(beta + c));
        r[j] = (t > 0.f) ? t : expm1f(t);
    }
    *(float4*)&g_h1a[(size_t)idx4 * 4] = make_float4(r[0], r[1], r[2], r[3]);
}

// ---------------- launch ----------------
extern "C" void kernel_launch(void* const* d_in, const int* in_sizes, int n_in,
                              void* d_out, int out_size) {
    const float* emb   = (const float*)d_in[0];
    const int*   ei    = (const int*)d_in[1];   // int32 or int64 (detected)
    const float* ew    = (const float*)d_in[2];
    const float* Wl1   = (const float*)d_in[3];
    const float* bl1   = (const float*)d_in[4];
    const float* Wr1   = (const float*)d_in[5];
    const float* br1   = (const float*)d_in[6];
    const float* We1   = (const float*)d_in[7];
    const float* att1  = (const float*)d_in[8];
    const float* bias1 = (const float*)d_in[9];
    const float* gamma1= (const float*)d_in[10];
    const float* beta1 = (const float*)d_in[11];
    const float* Wl2   = (const float*)d_in[12];
    const float* bl2   = (const float*)d_in[13];
    const float* Wr2   = (const float*)d_in[14];
    const float* br2   = (const float*)d_in[15];
    const float* We2   = (const float*)d_in[16];
    const float* att2  = (const float*)d_in[17];
    const float* bias2 = (const float*)d_in[18];
    float* out = (float*)d_out;

    const int n = in_sizes[0] / HC;   // 50000
    const int E = in_sizes[2];        // 800000

    dim3 ggrid((n + 127) / 128, 1, 2);

    // preprocessing + layer-1 GEMM (sgemm1 hoisted to slot 4 -> ncu profile target)
    zero_detect_kernel<<<(NN + 255) / 256, 256>>>(ei);
    deg_kernel<<<(E + 255) / 256, 256>>>(ei, ew, E);
    scan_part<<<NB_SCAN, 256>>>(n);
    sgemm_dual<<<ggrid, 256>>>(emb, Wl1, bl1, Wr1, br1, n, 0);   // 4th launch
    scan_mid<<<1, 256>>>(NB_SCAN, E + n);
    scan_final<<<NB_SCAN, 256>>>(n);
    csr_fill<<<(E + 255) / 256, 256>>>(ei, ew, E);
    self_fill<<<(n + 255) / 256, 256>>>(n);

    // layer 1 aggregation + BN/ELU
    gat_agg<<<(n + 1) / 2, 256>>>(We1, att1, bias1, nullptr, nullptr, 0, n);
    bn_stats<<<512, 128>>>(n);
    bn_apply<<<(n * (HC / 4) + 255) / 256, 256>>>(gamma1, beta1, n);

    // layer 2 (+ fused final combine)
    sgemm_dual<<<ggrid, 256>>>(nullptr, Wl2, bl2, Wr2, br2, n, 1);
    gat_agg<<<(n + 1) / 2, 256>>>(We2, att2, bias2, emb, out, 1, n);
}

// round 11
// speedup vs baseline: 1.1373x; 1.1373x over previous
#include <cuda_runtime.h>
#include <math.h>

// ---------------- problem constants ----------------
#define NN 50000
#define EE 800000
#define HC 128          // HEADS * C_OUT
#define NSLOT (EE + NN) // edges + self loops
#define NEG_SLOPE 0.2f
#define BN_EPS 1e-5f
#define NB_SCAN ((NN + 255) / 256)   // 196
#define LOG2E 1.44269504088896f

// ---------------- device-global scratch (no allocs allowed) ----------------
__device__ int    g_is64;
__device__ int    g_deg[NN];
__device__ int    g_cursor[NN];
__device__ float  g_wsum[NN];
__device__ int    g_rowstart[NN + 1];
__device__ int    g_part[256];
__device__ int    g_csrc[NSLOT];
__device__ float  g_cw[NSLOT];
__device__ float  g_xl[NN * HC];
__device__ float  g_xr[NN * HC];
__device__ float  g_h1[NN * HC];    // raw GAT1 output
__device__ float  g_h1a[NN * HC];   // after BN + ELU
__device__ double g_bnsum[HC], g_bnsq[HC];

// ---------------- f32x2 packed-FMA helpers (sm_100+) ----------------
__device__ __forceinline__ void ffma2(unsigned long long& d,
                                      unsigned long long a,
                                      unsigned long long b) {
    asm("fma.rn.f32x2 %0, %1, %2, %0;" : "+l"(d) : "l"(a), "l"(b));
}
__device__ __forceinline__ unsigned long long pack_dup(float x) {
    unsigned long long r;
    unsigned int u = __float_as_uint(x);
    asm("mov.b64 %0, {%1, %1};" : "=l"(r) : "r"(u));
    return r;
}
__device__ __forceinline__ void unpack2(unsigned long long v, float& lo, float& hi) {
    unsigned int a, b;
    asm("mov.b64 {%0, %1}, %2;" : "=r"(a), "=r"(b) : "l"(v));
    lo = __uint_as_float(a); hi = __uint_as_float(b);
}

// ---------------- helpers ----------------
// edge_index may be int64 (reference dtype) or int32 (JAX x64-off downcast).
// int64 little-endian with values < 2^31 -> every odd 32-bit word is zero.
__device__ __forceinline__ void load_edge(const int* __restrict__ ei, int e, int E,
                                          int& s, int& d) {
    if (g_is64) { s = ei[2 * e]; d = ei[2 * (E + e)]; }
    else        { s = ei[e];     d = ei[E + e]; }
}

// zero scratch + detect int64-vs-int32 layout (fused; one launch)
__global__ void zero_detect_kernel(const int* __restrict__ ei) {
    int i = blockIdx.x * blockDim.x + threadIdx.x;
    if (i < NN) { g_deg[i] = 0; g_wsum[i] = 0.f; g_cursor[i] = 0; }
    if (i < HC) { g_bnsum[i] = 0.0; g_bnsq[i] = 0.0; }
    if (blockIdx.x == 0 && threadIdx.x == 0) {
        int z = 0;
        #pragma unroll
        for (int j = 1; j < 64; j += 2) z |= ei[j];
        g_is64 = (z == 0) ? 1 : 0;
    }
}

__global__ void deg_kernel(const int* __restrict__ ei, const float* __restrict__ ew, int E) {
    int e = blockIdx.x * blockDim.x + threadIdx.x;
    if (e >= E) return;
    int s, d; load_edge(ei, e, E, s, d);
    (void)s;
    atomicAdd(&g_deg[d], 1);
    atomicAdd(&g_wsum[d], ew[e]);
}

// -------- 3-kernel exclusive scan over counts = deg[i] + 1 --------
__global__ void scan_part(int n) {
    __shared__ int sm[256];
    int tid = threadIdx.x;
    int i = blockIdx.x * 256 + tid;
    int v = (i < n) ? (g_deg[i] + 1) : 0;
    sm[tid] = v; __syncthreads();
    for (int off = 128; off > 0; off >>= 1) {
        if (tid < off) sm[tid] += sm[tid + off];
        __syncthreads();
    }
    if (tid == 0) g_part[blockIdx.x] = sm[0];
}

__global__ void scan_mid(int nb, int total) {
    __shared__ int sm[256];
    int tid = threadIdx.x;
    int v = (tid < nb) ? g_part[tid] : 0;
    sm[tid] = v; __syncthreads();
    for (int off = 1; off < 256; off <<= 1) {
        int t = (tid >= off) ? sm[tid - off] : 0;
        __syncthreads();
        sm[tid] += t;
        __syncthreads();
    }
    if (tid < nb) g_part[tid] = sm[tid] - v;   // exclusive
    if (tid == 0) g_rowstart[NN] = total;
}

__global__ void scan_final(int n) {
    __shared__ int sm[256];
    int tid = threadIdx.x;
    int i = blockIdx.x * 256 + tid;
    int v = (i < n) ? (g_deg[i] + 1) : 0;
    sm[tid] = v; __syncthreads();
    for (int off = 1; off < 256; off <<= 1) {
        int t = (tid >= off) ? sm[tid - off] : 0;
        __syncthreads();
        sm[tid] += t;
        __syncthreads();
    }
    if (i < n) g_rowstart[i] = g_part[blockIdx.x] + sm[tid] - v;   // exclusive
}

__global__ void csr_fill(const int* __restrict__ ei, const float* __restrict__ ew, int E) {
    int e = blockIdx.x * blockDim.x + threadIdx.x;
    if (e >= E) return;
    int s, d; load_edge(ei, e, E, s, d);
    int pos = atomicAdd(&g_cursor[d], 1);
    int slot = g_rowstart[d] + pos;
    g_csrc[slot] = s;
    g_cw[slot]   = ew[e];
}

// self loop fill; loop weight = mean incoming weight (0 if no in-edges)
__global__ void self_fill(int n) {
    int i = blockIdx.x * blockDim.x + threadIdx.x;
    if (i >= n) return;
    int slot = g_rowstart[i + 1] - 1;  // last slot of node i's segment
    g_csrc[slot] = i;
    g_cw[slot]   = g_wsum[i] / fmaxf((float)g_deg[i], 1.f);
}

// -------- SGEMM: O[M,128] = A[M,128] @ W[128,128] + b, dual-W via gridDim.z --------
// BM=BN=128, BK=8, 8x8 microtiles via packed fma.rn.f32x2 (2 fp32 FMA / instr;
// bit-identical fp32 math), 256 threads, register-prefetch pipelined.
__global__ __launch_bounds__(256) void sgemm_dual(
    const float* __restrict__ Aext,
    const float* __restrict__ W0, const float* __restrict__ b0,
    const float* __restrict__ W1, const float* __restrict__ b1,
    int M, int useH1a)
{
    const float* __restrict__ A    = useH1a ? g_h1a : Aext;
    const float* __restrict__ W    = blockIdx.z ? W1 : W0;
    const float* __restrict__ bias = blockIdx.z ? b1 : b0;
    float* __restrict__ O          = blockIdx.z ? g_xr : g_xl;

    __shared__ float As[8][128];  // [k][row]
    __shared__ float Bs[8][128];  // [k][col]

    int tid = threadIdx.x;
    int row0 = blockIdx.x * 128;
    int ty = tid / 16, tx = tid % 16;

    int a_r = tid >> 1;            // 0..127
    int a_c = (tid & 1) * 4;       // 0 or 4
    int b_r = tid >> 5;            // 0..7
    int b_c = (tid & 31) * 4;      // 0..124
    bool a_ok = (row0 + a_r) < M;
    const float* Aptr = A + (size_t)(row0 + a_r) * HC + a_c;
    const float* Wptr = W + b_r * 128 + b_c;

    // 8 rows x 4 column-pairs of packed f32x2 accumulators (= 8x8 floats)
    unsigned long long acc2[8][4];
    #pragma unroll
    for (int i = 0; i < 8; i++)
        #pragma unroll
        for (int j = 0; j < 4; j++) acc2[i][j] = 0ULL;   // bit pattern = {0.f, 0.f}

    // prologue loads for k0 = 0
    float4 av = a_ok ? *(const float4*)(Aptr) : make_float4(0.f, 0.f, 0.f, 0.f);
    float4 bv = *(const float4*)(Wptr);

    for (int k0 = 0; k0 < 128; k0 += 8) {
        __syncthreads();   // previous compute done reading smem
        As[a_c + 0][a_r] = av.x; As[a_c + 1][a_r] = av.y;
        As[a_c + 2][a_r] = av.z; As[a_c + 3][a_r] = av.w;
        *(float4*)&Bs[b_r][b_c] = bv;
        __syncthreads();
        if (k0 + 8 < 128) {   // prefetch next tile; latency hidden by FMAs below
            av = a_ok ? *(const float4*)(Aptr + k0 + 8) : make_float4(0.f, 0.f, 0.f, 0.f);
            bv = *(const float4*)(Wptr + (k0 + 8) * 128);
        }
        #pragma unroll
        for (int k = 0; k < 8; k++) {
            float4 ra0 = *(const float4*)&As[k][ty * 8];
            float4 ra1 = *(const float4*)&As[k][ty * 8 + 4];
            // rb pairs as raw 64-bit lanes (double2 = free bit-alias of 2 floats)
            double2 rb0 = *(const double2*)&Bs[k][tx * 8];
            double2 rb1 = *(const double2*)&Bs[k][tx * 8 + 4];
            unsigned long long b2[4];
            b2[0] = __double_as_longlong(rb0.x);
            b2[1] = __double_as_longlong(rb0.y);
            b2[2] = __double_as_longlong(rb1.x);
            b2[3] = __double_as_longlong(rb1.y);
            float ras[8] = {ra0.x, ra0.y, ra0.z, ra0.w, ra1.x, ra1.y, ra1.z, ra1.w};
            #pragma unroll
            for (int i = 0; i < 8; i++) {
                unsigned long long a2 = pack_dup(ras[i]);
                #pragma unroll
                for (int j = 0; j < 4; j++)
                    ffma2(acc2[i][j], a2, b2[j]);
            }
        }
    }

    #pragma unroll
    for (int i = 0; i < 8; i++) {
        int r = row0 + ty * 8 + i;
        if (r < M) {
            float o[8];
            #pragma unroll
            for (int j = 0; j < 4; j++) {
                float lo, hi;
                unpack2(acc2[i][j], lo, hi);
                o[2 * j]     = lo + __ldg(bias + tx * 8 + 2 * j);
                o[2 * j + 1] = hi + __ldg(bias + tx * 8 + 2 * j + 1);
            }
            *(float4*)(O + (size_t)r * HC + tx * 8)     = make_float4(o[0], o[1], o[2], o[3]);
            *(float4*)(O + (size_t)r * HC + tx * 8 + 4) = make_float4(o[4], o[5], o[6], o[7]);
        }
    }
}

// -------- GATv2 aggregation: one warp per (node, head), lane = channel --------
// R0-measured structure: 1 node/block, 128 threads, single online-softmax state,
// minimal registers (latency hidden by occupancy, not per-thread ILP).
// Only register-neutral change vs R0: base-2 softmax with log2e folded into att.
__global__ __launch_bounds__(128) void gat_agg(
    const float* __restrict__ We, const float* __restrict__ att,
    const float* __restrict__ bias,
    const float* __restrict__ emb, float* __restrict__ outFinal,
    int mode, int n)
{
    int node = blockIdx.x;
    if (node >= n) return;
    int col = threadIdx.x;                 // channel 0..127

    float att_v = __ldg(att + col) * LOG2E;   // base-2 softmax
    float we_v  = __ldg(We + col);
    float xr_v  = g_xr[(size_t)node * HC + col];
    int start = g_rowstart[node], end = g_rowstart[node + 1];

    float m = -INFINITY, s = 0.f, acc = 0.f;
    for (int i = start; i < end; ++i) {
        int   src = g_csrc[i];
        float w   = g_cw[i];
        float xlj = __ldg(g_xl + (size_t)src * HC + col);
        float t = fmaf(w, we_v, xlj + xr_v);
        t = fmaxf(t, NEG_SLOPE * t);
        float l = att_v * t;
        l += __shfl_xor_sync(0xffffffffu, l, 16);
        l += __shfl_xor_sync(0xffffffffu, l, 8);
        l += __shfl_xor_sync(0xffffffffu, l, 4);
        l += __shfl_xor_sync(0xffffffffu, l, 2);
        l += __shfl_xor_sync(0xffffffffu, l, 1);
        float nm = fmaxf(m, l);
        float sc = exp2f(m - nm);   // first iter: exp2(-inf) = 0
        float p  = exp2f(l - nm);
        s   = fmaf(s, sc, p);
        acc = fmaf(acc, sc, p * xlj);
        m = nm;
    }
    float v = acc / s + __ldg(bias + col);
    size_t idx = (size_t)node * HC + col;
    if (mode) {
        outFinal[idx] = (emb[idx] + g_h1a[idx] + v) * (1.f / 3.f);
    } else {
        g_h1[idx] = v;
    }
}

// -------- BatchNorm (training-style stats) + ELU --------
__global__ __launch_bounds__(128) void bn_stats(int n) {
    int c = threadIdx.x;
    float s = 0.f, q = 0.f;
    for (int r = blockIdx.x; r < n; r += gridDim.x) {
        float v = g_h1[(size_t)r * HC + c];
        s += v; q += v * v;
    }
    atomicAdd(&g_bnsum[c], (double)s);
    atomicAdd(&g_bnsq[c], (double)q);
}

// mu/inv computed inline from the double sums (no separate bn_fin launch).
// float4 path: 4 consecutive channels per thread.
__global__ void bn_apply(const float* __restrict__ gamma, const float* __restrict__ beta, int n) {
    int idx4 = blockIdx.x * blockDim.x + threadIdx.x;     // vec4 index
    if (idx4 >= n * (HC / 4)) return;
    int c4 = (idx4 & (HC / 4 - 1)) * 4;                   // first channel of group
    double inv_n = 1.0 / n;
    float4 v = *(const float4*)&g_h1[(size_t)idx4 * 4];
    float r[4] = {v.x, v.y, v.z, v.w};
    #pragma unroll
    for (int j = 0; j < 4; j++) {
        int c = c4 + j;
        double mu = g_bnsum[c] * inv_n;
        double var = g_bnsq[c] * inv_n - mu * mu;
        float inv = rsqrtf((float)var + BN_EPS);
        float t = fmaf(__ldg(gamma + c) * (r[j] - (float)mu), inv, __ldg(beta + c));
        r[j] = (t > 0.f) ? t : expm1f(t);
    }
    *(float4*)&g_h1a[(size_t)idx4 * 4] = make_float4(r[0], r[1], r[2], r[3]);
}

// ---------------- launch ----------------
extern "C" void kernel_launch(void* const* d_in, const int* in_sizes, int n_in,
                              void* d_out, int out_size) {
    const float* emb   = (const float*)d_in[0];
    const int*   ei    = (const int*)d_in[1];   // int32 or int64 (detected)
    const float* ew    = (const float*)d_in[2];
    const float* Wl1   = (const float*)d_in[3];
    const float* bl1   = (const float*)d_in[4];
    const float* Wr1   = (const float*)d_in[5];
    const float* br1   = (const float*)d_in[6];
    const float* We1   = (const float*)d_in[7];
    const float* att1  = (const float*)d_in[8];
    const float* bias1 = (const float*)d_in[9];
    const float* gamma1= (const float*)d_in[10];
    const float* beta1 = (const float*)d_in[11];
    const float* Wl2   = (const float*)d_in[12];
    const float* bl2   = (const float*)d_in[13];
    const float* Wr2   = (const float*)d_in[14];
    const float* br2   = (const float*)d_in[15];
    const float* We2   = (const float*)d_in[16];
    const float* att2  = (const float*)d_in[17];
    const float* bias2 = (const float*)d_in[18];
    float* out = (float*)d_out;

    const int n = in_sizes[0] / HC;   // 50000
    const int E = in_sizes[2];        // 800000

    dim3 ggrid((n + 127) / 128, 1, 2);

    // preprocessing + layer-1 GEMM (sgemm1 hoisted to slot 4 -> ncu profile target)
    zero_detect_kernel<<<(NN + 255) / 256, 256>>>(ei);
    deg_kernel<<<(E + 255) / 256, 256>>>(ei, ew, E);
    scan_part<<<NB_SCAN, 256>>>(n);
    sgemm_dual<<<ggrid, 256>>>(emb, Wl1, bl1, Wr1, br1, n, 0);   // 4th launch
    scan_mid<<<1, 256>>>(NB_SCAN, E + n);
    scan_final<<<NB_SCAN, 256>>>(n);
    csr_fill<<<(E + 255) / 256, 256>>>(ei, ew, E);
    self_fill<<<(n + 255) / 256, 256>>>(n);

    // layer 1 aggregation + BN/ELU
    gat_agg<<<n, 128>>>(We1, att1, bias1, nullptr, nullptr, 0, n);
    bn_stats<<<512, 128>>>(n);
    bn_apply<<<(n * (HC / 4) + 255) / 256, 256>>>(gamma1, beta1, n);

    // layer 2 (+ fused final combine)
    sgemm_dual<<<ggrid, 256>>>(nullptr, Wl2, bl2, Wr2, br2, n, 1);
    gat_agg<<<n, 128>>>(We2, att2, bias2, emb, out, 1, n);
}

// round 12
// speedup vs baseline: 1.1869x; 1.0436x over previous
#include <cuda_runtime.h>
#include <math.h>

// ---------------- problem constants ----------------
#define NN 50000
#define EE 800000
#define HC 128          // HEADS * C_OUT
#define NSLOT (EE + NN) // edges + self loops
#define NEG_SLOPE 0.2f
#define BN_EPS 1e-5f
#define NB_SCAN ((NN + 255) / 256)   // 196
#define LOG2E 1.44269504088896f

// ---------------- device-global scratch (no allocs allowed) ----------------
__device__ int    g_is64;
__device__ int    g_deg[NN];
__device__ int    g_cursor[NN];
__device__ float  g_wsum[NN];
__device__ int    g_rowstart[NN + 1];
__device__ int    g_part[256];
__device__ int    g_csrc[NSLOT];
__device__ float  g_cw[NSLOT];
__device__ float  g_xl[NN * HC];
__device__ float  g_xr[NN * HC];
__device__ float  g_h1[NN * HC];    // raw GAT1 output
__device__ float  g_h1a[NN * HC];   // after BN + ELU
__device__ double g_bnsum[HC], g_bnsq[HC];

// ---------------- f32x2 packed-FMA helpers (sm_100+) ----------------
__device__ __forceinline__ void ffma2(unsigned long long& d,
                                      unsigned long long a,
                                      unsigned long long b) {
    asm("fma.rn.f32x2 %0, %1, %2, %0;" : "+l"(d) : "l"(a), "l"(b));
}
__device__ __forceinline__ unsigned long long pack_dup(float x) {
    unsigned long long r;
    unsigned int u = __float_as_uint(x);
    asm("mov.b64 %0, {%1, %1};" : "=l"(r) : "r"(u));
    return r;
}
__device__ __forceinline__ void unpack2(unsigned long long v, float& lo, float& hi) {
    unsigned int a, b;
    asm("mov.b64 {%0, %1}, %2;" : "=r"(a), "=r"(b) : "l"(v));
    lo = __uint_as_float(a); hi = __uint_as_float(b);
}

// ---------------- helpers ----------------
// edge_index may be int64 (reference dtype) or int32 (JAX x64-off downcast).
// int64 little-endian with values < 2^31 -> every odd 32-bit word is zero.
__device__ __forceinline__ void load_edge(const int* __restrict__ ei, int e, int E,
                                          int& s, int& d) {
    if (g_is64) { s = ei[2 * e]; d = ei[2 * (E + e)]; }
    else        { s = ei[e];     d = ei[E + e]; }
}

// zero scratch + detect int64-vs-int32 layout (fused; one launch)
__global__ void zero_detect_kernel(const int* __restrict__ ei) {
    int i = blockIdx.x * blockDim.x + threadIdx.x;
    if (i < NN) { g_deg[i] = 0; g_wsum[i] = 0.f; g_cursor[i] = 0; }
    if (i < HC) { g_bnsum[i] = 0.0; g_bnsq[i] = 0.0; }
    if (blockIdx.x == 0 && threadIdx.x == 0) {
        int z = 0;
        #pragma unroll
        for (int j = 1; j < 64; j += 2) z |= ei[j];
        g_is64 = (z == 0) ? 1 : 0;
    }
}

__global__ void deg_kernel(const int* __restrict__ ei, const float* __restrict__ ew, int E) {
    int e = blockIdx.x * blockDim.x + threadIdx.x;
    if (e >= E) return;
    int s, d; load_edge(ei, e, E, s, d);
    (void)s;
    atomicAdd(&g_deg[d], 1);
    atomicAdd(&g_wsum[d], ew[e]);
}

// -------- 3-kernel exclusive scan over counts = deg[i] + 1 --------
__global__ void scan_part(int n) {
    __shared__ int sm[256];
    int tid = threadIdx.x;
    int i = blockIdx.x * 256 + tid;
    int v = (i < n) ? (g_deg[i] + 1) : 0;
    sm[tid] = v; __syncthreads();
    for (int off = 128; off > 0; off >>= 1) {
        if (tid < off) sm[tid] += sm[tid + off];
        __syncthreads();
    }
    if (tid == 0) g_part[blockIdx.x] = sm[0];
}

__global__ void scan_mid(int nb, int total) {
    __shared__ int sm[256];
    int tid = threadIdx.x;
    int v = (tid < nb) ? g_part[tid] : 0;
    sm[tid] = v; __syncthreads();
    for (int off = 1; off < 256; off <<= 1) {
        int t = (tid >= off) ? sm[tid - off] : 0;
        __syncthreads();
        sm[tid] += t;
        __syncthreads();
    }
    if (tid < nb) g_part[tid] = sm[tid] - v;   // exclusive
    if (tid == 0) g_rowstart[NN] = total;
}

__global__ void scan_final(int n) {
    __shared__ int sm[256];
    int tid = threadIdx.x;
    int i = blockIdx.x * 256 + tid;
    int v = (i < n) ? (g_deg[i] + 1) : 0;
    sm[tid] = v; __syncthreads();
    for (int off = 1; off < 256; off <<= 1) {
        int t = (tid >= off) ? sm[tid - off] : 0;
        __syncthreads();
        sm[tid] += t;
        __syncthreads();
    }
    if (i < n) g_rowstart[i] = g_part[blockIdx.x] + sm[tid] - v;   // exclusive
}

__global__ void csr_fill(const int* __restrict__ ei, const float* __restrict__ ew, int E) {
    int e = blockIdx.x * blockDim.x + threadIdx.x;
    if (e >= E) return;
    int s, d; load_edge(ei, e, E, s, d);
    int pos = atomicAdd(&g_cursor[d], 1);
    int slot = g_rowstart[d] + pos;
    g_csrc[slot] = s;
    g_cw[slot]   = ew[e];
}

// self loop fill; loop weight = mean incoming weight (0 if no in-edges)
__global__ void self_fill(int n) {
    int i = blockIdx.x * blockDim.x + threadIdx.x;
    if (i >= n) return;
    int slot = g_rowstart[i + 1] - 1;  // last slot of node i's segment
    g_csrc[slot] = i;
    g_cw[slot]   = g_wsum[i] / fmaxf((float)g_deg[i], 1.f);
}

// -------- SGEMM: O[M,128] = A[M,128] @ W[128,128] + b, dual-W via gridDim.z --------
// BM=BN=128, BK=8, 8x8 microtiles via packed fma.rn.f32x2, 256 threads,
// register-prefetch pipelined. Each thread owns two 4-col blocks (tx*4 and
// 64+tx*4): B smem reads are LDS.128 at 16B lane stride -> conflict-free
// (the old tx*8 mapping put lanes at 32B stride = 4-way bank conflict, which
// made the kernel smem-crossbar-bound per R11 ncu: L1=70%, issue=35%).
__global__ __launch_bounds__(256) void sgemm_dual(
    const float* __restrict__ Aext,
    const float* __restrict__ W0, const float* __restrict__ b0,
    const float* __restrict__ W1, const float* __restrict__ b1,
    int M, int useH1a)
{
    const float* __restrict__ A    = useH1a ? g_h1a : Aext;
    const float* __restrict__ W    = blockIdx.z ? W1 : W0;
    const float* __restrict__ bias = blockIdx.z ? b1 : b0;
    float* __restrict__ O          = blockIdx.z ? g_xr : g_xl;

    __shared__ float As[8][128];  // [k][row]
    __shared__ float Bs[8][128];  // [k][col]

    int tid = threadIdx.x;
    int row0 = blockIdx.x * 128;
    int ty = tid / 16, tx = tid % 16;
    int c0 = tx * 4;          // first 4-col block
    int c1 = 64 + tx * 4;     // second 4-col block

    int a_r = tid >> 1;            // 0..127
    int a_c = (tid & 1) * 4;       // 0 or 4
    int b_r = tid >> 5;            // 0..7
    int b_c = (tid & 31) * 4;      // 0..124
    bool a_ok = (row0 + a_r) < M;
    const float* Aptr = A + (size_t)(row0 + a_r) * HC + a_c;
    const float* Wptr = W + b_r * 128 + b_c;

    // 8 rows x 4 column-pairs of packed f32x2 accumulators (= 8x8 floats)
    // j=0,1 -> cols c0..c0+3 ; j=2,3 -> cols c1..c1+3
    unsigned long long acc2[8][4];
    #pragma unroll
    for (int i = 0; i < 8; i++)
        #pragma unroll
        for (int j = 0; j < 4; j++) acc2[i][j] = 0ULL;   // bit pattern = {0.f, 0.f}

    // prologue loads for k0 = 0
    float4 av = a_ok ? *(const float4*)(Aptr) : make_float4(0.f, 0.f, 0.f, 0.f);
    float4 bv = *(const float4*)(Wptr);

    for (int k0 = 0; k0 < 128; k0 += 8) {
        __syncthreads();   // previous compute done reading smem
        As[a_c + 0][a_r] = av.x; As[a_c + 1][a_r] = av.y;
        As[a_c + 2][a_r] = av.z; As[a_c + 3][a_r] = av.w;
        *(float4*)&Bs[b_r][b_c] = bv;
        __syncthreads();
        if (k0 + 8 < 128) {   // prefetch next tile; latency hidden by FMAs below
            av = a_ok ? *(const float4*)(Aptr + k0 + 8) : make_float4(0.f, 0.f, 0.f, 0.f);
            bv = *(const float4*)(Wptr + (k0 + 8) * 128);
        }
        #pragma unroll
        for (int k = 0; k < 8; k++) {
            float4 ra0 = *(const float4*)&As[k][ty * 8];
            float4 ra1 = *(const float4*)&As[k][ty * 8 + 4];
            // two conflict-free LDS.128: lanes at 16B stride, 256B contiguous
            double2 rb0 = *(const double2*)&Bs[k][c0];
            double2 rb1 = *(const double2*)&Bs[k][c1];
            unsigned long long b2[4];
            b2[0] = __double_as_longlong(rb0.x);
            b2[1] = __double_as_longlong(rb0.y);
            b2[2] = __double_as_longlong(rb1.x);
            b2[3] = __double_as_longlong(rb1.y);
            float ras[8] = {ra0.x, ra0.y, ra0.z, ra0.w, ra1.x, ra1.y, ra1.z, ra1.w};
            #pragma unroll
            for (int i = 0; i < 8; i++) {
                unsigned long long a2 = pack_dup(ras[i]);
                #pragma unroll
                for (int j = 0; j < 4; j++)
                    ffma2(acc2[i][j], a2, b2[j]);
            }
        }
    }

    #pragma unroll
    for (int i = 0; i < 8; i++) {
        int r = row0 + ty * 8 + i;
        if (r < M) {
            float o[8];
            #pragma unroll
            for (int j = 0; j < 2; j++) {       // block c0
                float lo, hi;
                unpack2(acc2[i][j], lo, hi);
                o[2 * j]     = lo + __ldg(bias + c0 + 2 * j);
                o[2 * j + 1] = hi + __ldg(bias + c0 + 2 * j + 1);
            }
            #pragma unroll
            for (int j = 2; j < 4; j++) {       // block c1
                float lo, hi;
                unpack2(acc2[i][j], lo, hi);
                o[2 * j]     = lo + __ldg(bias + c1 + 2 * (j - 2));
                o[2 * j + 1] = hi + __ldg(bias + c1 + 2 * (j - 2) + 1);
            }
            *(float4*)(O + (size_t)r * HC + c0) = make_float4(o[0], o[1], o[2], o[3]);
            *(float4*)(O + (size_t)r * HC + c1) = make_float4(o[4], o[5], o[6], o[7]);
        }
    }
}

// -------- GATv2 aggregation: one warp per (node, head), lane = channel --------
// R0-measured structure: 1 node/block, 128 threads, single online-softmax state,
// minimal registers (latency hidden by occupancy, not per-thread ILP).
__global__ __launch_bounds__(128) void gat_agg(
    const float* __restrict__ We, const float* __restrict__ att,
    const float* __restrict__ bias,
    const float* __restrict__ emb, float* __restrict__ outFinal,
    int mode, int n)
{
    int node = blockIdx.x;
    if (node >= n) return;
    int col = threadIdx.x;                 // channel 0..127

    float att_v = __ldg(att + col) * LOG2E;   // base-2 softmax
    float we_v  = __ldg(We + col);
    float xr_v  = g_xr[(size_t)node * HC + col];
    int start = g_rowstart[node], end = g_rowstart[node + 1];

    float m = -INFINITY, s = 0.f, acc = 0.f;
    for (int i = start; i < end; ++i) {
        int   src = g_csrc[i];
        float w   = g_cw[i];
        float xlj = __ldg(g_xl + (size_t)src * HC + col);
        float t = fmaf(w, we_v, xlj + xr_v);
        t = fmaxf(t, NEG_SLOPE * t);
        float l = att_v * t;
        l += __shfl_xor_sync(0xffffffffu, l, 16);
        l += __shfl_xor_sync(0xffffffffu, l, 8);
        l += __shfl_xor_sync(0xffffffffu, l, 4);
        l += __shfl_xor_sync(0xffffffffu, l, 2);
        l += __shfl_xor_sync(0xffffffffu, l, 1);
        float nm = fmaxf(m, l);
        float sc = exp2f(m - nm);   // first iter: exp2(-inf) = 0
        float p  = exp2f(l - nm);
        s   = fmaf(s, sc, p);
        acc = fmaf(acc, sc, p * xlj);
        m = nm;
    }
    float v = acc / s + __ldg(bias + col);
    size_t idx = (size_t)node * HC + col;
    if (mode) {
        outFinal[idx] = (emb[idx] + g_h1a[idx] + v) * (1.f / 3.f);
    } else {
        g_h1[idx] = v;
    }
}

// -------- BatchNorm (training-style stats) + ELU --------
__global__ __launch_bounds__(128) void bn_stats(int n) {
    int c = threadIdx.x;
    float s = 0.f, q = 0.f;
    for (int r = blockIdx.x; r < n; r += gridDim.x) {
        float v = g_h1[(size_t)r * HC + c];
        s += v; q += v * v;
    }
    atomicAdd(&g_bnsum[c], (double)s);
    atomicAdd(&g_bnsq[c], (double)q);
}

// mu/inv computed inline from the double sums (no separate bn_fin launch).
// float4 path: 4 consecutive channels per thread.
__global__ void bn_apply(const float* __restrict__ gamma, const float* __restrict__ beta, int n) {
    int idx4 = blockIdx.x * blockDim.x + threadIdx.x;     // vec4 index
    if (idx4 >= n * (HC / 4)) return;
    int c4 = (idx4 & (HC / 4 - 1)) * 4;                   // first channel of group
    double inv_n = 1.0 / n;
    float4 v = *(const float4*)&g_h1[(size_t)idx4 * 4];
    float r[4] = {v.x, v.y, v.z, v.w};
    #pragma unroll
    for (int j = 0; j < 4; j++) {
        int c = c4 + j;
        double mu = g_bnsum[c] * inv_n;
        double var = g_bnsq[c] * inv_n - mu * mu;
        float inv = rsqrtf((float)var + BN_EPS);
        float t = fmaf(__ldg(gamma + c) * (r[j] - (float)mu), inv, __ldg(beta + c));
        r[j] = (t > 0.f) ? t : expm1f(t);
    }
    *(float4*)&g_h1a[(size_t)idx4 * 4] = make_float4(r[0], r[1], r[2], r[3]);
}

// ---------------- launch ----------------
extern "C" void kernel_launch(void* const* d_in, const int* in_sizes, int n_in,
                              void* d_out, int out_size) {
    const float* emb   = (const float*)d_in[0];
    const int*   ei    = (const int*)d_in[1];   // int32 or int64 (detected)
    const float* ew    = (const float*)d_in[2];
    const float* Wl1   = (const float*)d_in[3];
    const float* bl1   = (const float*)d_in[4];
    const float* Wr1   = (const float*)d_in[5];
    const float* br1   = (const float*)d_in[6];
    const float* We1   = (const float*)d_in[7];
    const float* att1  = (const float*)d_in[8];
    const float* bias1 = (const float*)d_in[9];
    const float* gamma1= (const float*)d_in[10];
    const float* beta1 = (const float*)d_in[11];
    const float* Wl2   = (const float*)d_in[12];
    const float* bl2   = (const float*)d_in[13];
    const float* Wr2   = (const float*)d_in[14];
    const float* br2   = (const float*)d_in[15];
    const float* We2   = (const float*)d_in[16];
    const float* att2  = (const float*)d_in[17];
    const float* bias2 = (const float*)d_in[18];
    float* out = (float*)d_out;

    const int n = in_sizes[0] / HC;   // 50000
    const int E = in_sizes[2];        // 800000

    dim3 ggrid((n + 127) / 128, 1, 2);

    // preprocessing + layer-1 GEMM (sgemm1 hoisted to slot 4 -> ncu profile target)
    zero_detect_kernel<<<(NN + 255) / 256, 256>>>(ei);
    deg_kernel<<<(E + 255) / 256, 256>>>(ei, ew, E);
    scan_part<<<NB_SCAN, 256>>>(n);
    sgemm_dual<<<ggrid, 256>>>(emb, Wl1, bl1, Wr1, br1, n, 0);   // 4th launch
    scan_mid<<<1, 256>>>(NB_SCAN, E + n);
    scan_final<<<NB_SCAN, 256>>>(n);
    csr_fill<<<(E + 255) / 256, 256>>>(ei, ew, E);
    self_fill<<<(n + 255) / 256, 256>>>(n);

    // layer 1 aggregation + BN/ELU
    gat_agg<<<n, 128>>>(We1, att1, bias1, nullptr, nullptr, 0, n);
    bn_stats<<<512, 128>>>(n);
    bn_apply<<<(n * (HC / 4) + 255) / 256, 256>>>(gamma1, beta1, n);

    // layer 2 (+ fused final combine)
    sgemm_dual<<<ggrid, 256>>>(nullptr, Wl2, bl2, Wr2, br2, n, 1);
    gat_agg<<<n, 128>>>(We2, att2, bias2, emb, out, 1, n);
}

// round 13
// speedup vs baseline: 1.2984x; 1.0939x over previous
#include <cuda_runtime.h>
#include <math.h>

// ---------------- problem constants ----------------
#define NN 50000
#define EE 800000
#define HC 128          // HEADS * C_OUT
#define NSLOT (EE + NN) // edges + self loops
#define NEG_SLOPE 0.2f
#define BN_EPS 1e-5f
#define NB_SCAN ((NN + 255) / 256)   // 196
#define LOG2E 1.44269504088896f

// ---------------- device-global scratch (no allocs allowed) ----------------
__device__ int    g_is64;
__device__ int    g_deg[NN];
__device__ int    g_cursor[NN];
__device__ float  g_wsum[NN];
__device__ int    g_rowstart[NN + 1];
__device__ int    g_part[256];
__device__ int    g_csrc[NSLOT];
__device__ float  g_cw[NSLOT];
__device__ float  g_xl[NN * HC];
__device__ float  g_xr[NN * HC];
__device__ float  g_h1[NN * HC];    // raw GAT1 output
__device__ float  g_h1a[NN * HC];   // after BN + ELU
__device__ double g_bnsum[HC], g_bnsq[HC];

// ---------------- f32x2 packed-FMA helpers (sm_100+) ----------------
__device__ __forceinline__ void ffma2(unsigned long long& d,
                                      unsigned long long a,
                                      unsigned long long b) {
    asm("fma.rn.f32x2 %0, %1, %2, %0;" : "+l"(d) : "l"(a), "l"(b));
}
__device__ __forceinline__ unsigned long long pack_dup(float x) {
    unsigned long long r;
    unsigned int u = __float_as_uint(x);
    asm("mov.b64 %0, {%1, %1};" : "=l"(r) : "r"(u));
    return r;
}
__device__ __forceinline__ void unpack2(unsigned long long v, float& lo, float& hi) {
    unsigned int a, b;
    asm("mov.b64 {%0, %1}, %2;" : "=r"(a), "=r"(b) : "l"(v));
    lo = __uint_as_float(a); hi = __uint_as_float(b);
}

// ---------------- helpers ----------------
// edge_index may be int64 (reference dtype) or int32 (JAX x64-off downcast).
// int64 little-endian with values < 2^31 -> every odd 32-bit word is zero.
__device__ __forceinline__ void load_edge(const int* __restrict__ ei, int e, int E,
                                          int& s, int& d) {
    if (g_is64) { s = ei[2 * e]; d = ei[2 * (E + e)]; }
    else        { s = ei[e];     d = ei[E + e]; }
}

// zero scratch + detect int64-vs-int32 layout (fused; one launch)
__global__ void zero_detect_kernel(const int* __restrict__ ei) {
    int i = blockIdx.x * blockDim.x + threadIdx.x;
    if (i < NN) { g_deg[i] = 0; g_wsum[i] = 0.f; g_cursor[i] = 0; }
    if (i < HC) { g_bnsum[i] = 0.0; g_bnsq[i] = 0.0; }
    if (blockIdx.x == 0 && threadIdx.x == 0) {
        int z = 0;
        #pragma unroll
        for (int j = 1; j < 64; j += 2) z |= ei[j];
        g_is64 = (z == 0) ? 1 : 0;
    }
}

__global__ void deg_kernel(const int* __restrict__ ei, const float* __restrict__ ew, int E) {
    int e = blockIdx.x * blockDim.x + threadIdx.x;
    if (e >= E) return;
    int s, d; load_edge(ei, e, E, s, d);
    (void)s;
    atomicAdd(&g_deg[d], 1);
    atomicAdd(&g_wsum[d], ew[e]);
}

// -------- 3-kernel exclusive scan over counts = deg[i] + 1 --------
__global__ void scan_part(int n) {
    __shared__ int sm[256];
    int tid = threadIdx.x;
    int i = blockIdx.x * 256 + tid;
    int v = (i < n) ? (g_deg[i] + 1) : 0;
    sm[tid] = v; __syncthreads();
    for (int off = 128; off > 0; off >>= 1) {
        if (tid < off) sm[tid] += sm[tid + off];
        __syncthreads();
    }
    if (tid == 0) g_part[blockIdx.x] = sm[0];
}

__global__ void scan_mid(int nb, int total) {
    __shared__ int sm[256];
    int tid = threadIdx.x;
    int v = (tid < nb) ? g_part[tid] : 0;
    sm[tid] = v; __syncthreads();
    for (int off = 1; off < 256; off <<= 1) {
        int t = (tid >= off) ? sm[tid - off] : 0;
        __syncthreads();
        sm[tid] += t;
        __syncthreads();
    }
    if (tid < nb) g_part[tid] = sm[tid] - v;   // exclusive
    if (tid == 0) g_rowstart[NN] = total;
}

__global__ void scan_final(int n) {
    __shared__ int sm[256];
    int tid = threadIdx.x;
    int i = blockIdx.x * 256 + tid;
    int v = (i < n) ? (g_deg[i] + 1) : 0;
    sm[tid] = v; __syncthreads();
    for (int off = 1; off < 256; off <<= 1) {
        int t = (tid >= off) ? sm[tid - off] : 0;
        __syncthreads();
        sm[tid] += t;
        __syncthreads();
    }
    if (i < n) g_rowstart[i] = g_part[blockIdx.x] + sm[tid] - v;   // exclusive
}

__global__ void csr_fill(const int* __restrict__ ei, const float* __restrict__ ew, int E) {
    int e = blockIdx.x * blockDim.x + threadIdx.x;
    if (e >= E) return;
    int s, d; load_edge(ei, e, E, s, d);
    int pos = atomicAdd(&g_cursor[d], 1);
    int slot = g_rowstart[d] + pos;
    g_csrc[slot] = s;
    g_cw[slot]   = ew[e];
}

// self loop fill; loop weight = mean incoming weight (0 if no in-edges)
__global__ void self_fill(int n) {
    int i = blockIdx.x * blockDim.x + threadIdx.x;
    if (i >= n) return;
    int slot = g_rowstart[i + 1] - 1;  // last slot of node i's segment
    g_csrc[slot] = i;
    g_cw[slot]   = g_wsum[i] / fmaxf((float)g_deg[i], 1.f);
}

// -------- SGEMM: O[M,128] = A[M,128] @ W[128,128] + b, dual-W via gridDim.z --------
// BM=BN=128, BK=8, 8x8 microtiles via packed fma.rn.f32x2, 256 threads.
// Double-buffered smem (ping-pong): ONE __syncthreads per K-tile; compute reads
// the stage stored LAST iteration, so store->sync->use serialization is gone
// (R12 ncu: 40us of the 87.7us was sync/latency exposure over the 48us FFMA2
// issue floor). Conflict-free B reads (two 4-col blocks at tx*4 / 64+tx*4).
__global__ __launch_bounds__(256) void sgemm_dual(
    const float* __restrict__ Aext,
    const float* __restrict__ W0, const float* __restrict__ b0,
    const float* __restrict__ W1, const float* __restrict__ b1,
    int M, int useH1a)
{
    const float* __restrict__ A    = useH1a ? g_h1a : Aext;
    const float* __restrict__ W    = blockIdx.z ? W1 : W0;
    const float* __restrict__ bias = blockIdx.z ? b1 : b0;
    float* __restrict__ O          = blockIdx.z ? g_xr : g_xl;

    __shared__ float As[2][8][128];  // [stage][k][row]
    __shared__ float Bs[2][8][128];  // [stage][k][col]

    int tid = threadIdx.x;
    int row0 = blockIdx.x * 128;
    int ty = tid / 16, tx = tid % 16;
    int c0 = tx * 4;          // first 4-col block
    int c1 = 64 + tx * 4;     // second 4-col block

    int a_r = tid >> 1;            // 0..127
    int a_c = (tid & 1) * 4;       // 0 or 4
    int b_r = tid >> 5;            // 0..7
    int b_c = (tid & 31) * 4;      // 0..124
    bool a_ok = (row0 + a_r) < M;
    const float* Aptr = A + (size_t)(row0 + a_r) * HC + a_c;
    const float* Wptr = W + b_r * 128 + b_c;

    // 8 rows x 4 column-pairs of packed f32x2 accumulators (= 8x8 floats)
    unsigned long long acc2[8][4];
    #pragma unroll
    for (int i = 0; i < 8; i++)
        #pragma unroll
        for (int j = 0; j < 4; j++) acc2[i][j] = 0ULL;

    // prologue: load + store K-tile 0 into stage 0
    {
        float4 av0 = a_ok ? *(const float4*)(Aptr) : make_float4(0.f, 0.f, 0.f, 0.f);
        float4 bv0 = *(const float4*)(Wptr);
        As[0][a_c + 0][a_r] = av0.x; As[0][a_c + 1][a_r] = av0.y;
        As[0][a_c + 2][a_r] = av0.z; As[0][a_c + 3][a_r] = av0.w;
        *(float4*)&Bs[0][b_r][b_c] = bv0;
    }
    __syncthreads();

    int p = 0;
    for (int k0 = 0; k0 < 128; k0 += 8) {
        float4 av, bv;
        bool more = (k0 + 8 < 128);
        if (more) {    // prefetch next tile from global; latency hidden by compute
            av = a_ok ? *(const float4*)(Aptr + k0 + 8) : make_float4(0.f, 0.f, 0.f, 0.f);
            bv = *(const float4*)(Wptr + (k0 + 8) * 128);
        }
        #pragma unroll
        for (int k = 0; k < 8; k++) {
            float4 ra0 = *(const float4*)&As[p][k][ty * 8];
            float4 ra1 = *(const float4*)&As[p][k][ty * 8 + 4];
            double2 rb0 = *(const double2*)&Bs[p][k][c0];
            double2 rb1 = *(const double2*)&Bs[p][k][c1];
            unsigned long long b2[4];
            b2[0] = __double_as_longlong(rb0.x);
            b2[1] = __double_as_longlong(rb0.y);
            b2[2] = __double_as_longlong(rb1.x);
            b2[3] = __double_as_longlong(rb1.y);
            float ras[8] = {ra0.x, ra0.y, ra0.z, ra0.w, ra1.x, ra1.y, ra1.z, ra1.w};
            #pragma unroll
            for (int i = 0; i < 8; i++) {
                unsigned long long a2 = pack_dup(ras[i]);
                #pragma unroll
                for (int j = 0; j < 4; j++)
                    ffma2(acc2[i][j], a2, b2[j]);
            }
        }
        if (more) {    // store into the idle stage; nobody reads it until after sync
            int q = p ^ 1;
            As[q][a_c + 0][a_r] = av.x; As[q][a_c + 1][a_r] = av.y;
            As[q][a_c + 2][a_r] = av.z; As[q][a_c + 3][a_r] = av.w;
            *(float4*)&Bs[q][b_r][b_c] = bv;
            __syncthreads();
            p = q;
        }
    }

    #pragma unroll
    for (int i = 0; i < 8; i++) {
        int r = row0 + ty * 8 + i;
        if (r < M) {
            float o[8];
            #pragma unroll
            for (int j = 0; j < 2; j++) {       // block c0
                float lo, hi;
                unpack2(acc2[i][j], lo, hi);
                o[2 * j]     = lo + __ldg(bias + c0 + 2 * j);
                o[2 * j + 1] = hi + __ldg(bias + c0 + 2 * j + 1);
            }
            #pragma unroll
            for (int j = 2; j < 4; j++) {       // block c1
                float lo, hi;
                unpack2(acc2[i][j], lo, hi);
                o[2 * j]     = lo + __ldg(bias + c1 + 2 * (j - 2));
                o[2 * j + 1] = hi + __ldg(bias + c1 + 2 * (j - 2) + 1);
            }
            *(float4*)(O + (size_t)r * HC + c0) = make_float4(o[0], o[1], o[2], o[3]);
            *(float4*)(O + (size_t)r * HC + c1) = make_float4(o[4], o[5], o[6], o[7]);
        }
    }
}

// -------- GATv2 aggregation: 2 channels per thread (float2) --------
// Warp covers 64 channels = 2 heads (16 lanes x 2ch per head). Head logit
// reduce = 4 shfl levels (xor 8/4/2/1 stays inside each 16-lane group).
// Halves warps per node (4 -> 2) and instructions per edge-channel vs the
// scalar version; registers stay low (~45) so occupancy is preserved (R7
// lesson: this kernel hides latency with TLP, not per-thread ILP).
// 2 nodes per 128-thread block.
__global__ __launch_bounds__(128) void gat_agg(
    const float* __restrict__ We, const float* __restrict__ att,
    const float* __restrict__ bias,
    const float* __restrict__ emb, float* __restrict__ outFinal,
    int mode, int n)
{
    int node = blockIdx.x * 2 + (threadIdx.x >> 6);
    if (node >= n) return;
    int c2 = (threadIdx.x & 63) * 2;       // first of this thread's 2 channels

    float2 att_v = *(const float2*)(att + c2);
    att_v.x *= LOG2E; att_v.y *= LOG2E;    // base-2 softmax
    float2 we_v = *(const float2*)(We + c2);
    float2 xr_v = *(const float2*)(g_xr + (size_t)node * HC + c2);
    int start = g_rowstart[node], end = g_rowstart[node + 1];

    float m = -INFINITY, s = 0.f;
    float ax = 0.f, ay = 0.f;
    for (int i = start; i < end; ++i) {
        int   src = g_csrc[i];
        float w   = g_cw[i];
        float2 xl = *(const float2*)(g_xl + (size_t)src * HC + c2);
        float t0 = fmaf(w, we_v.x, xl.x + xr_v.x); t0 = fmaxf(t0, NEG_SLOPE * t0);
        float t1 = fmaf(w, we_v.y, xl.y + xr_v.y); t1 = fmaxf(t1, NEG_SLOPE * t1);
        float l = fmaf(att_v.x, t0, att_v.y * t1);
        l += __shfl_xor_sync(0xffffffffu, l, 8);
        l += __shfl_xor_sync(0xffffffffu, l, 4);
        l += __shfl_xor_sync(0xffffffffu, l, 2);
        l += __shfl_xor_sync(0xffffffffu, l, 1);
        float nm = fmaxf(m, l);
        float sc = exp2f(m - nm);   // first iter: exp2(-inf) = 0
        float p  = exp2f(l - nm);
        s  = fmaf(s, sc, p);
        ax = fmaf(ax, sc, p * xl.x);
        ay = fmaf(ay, sc, p * xl.y);
        m = nm;
    }
    float2 bias_v = *(const float2*)(bias + c2);
    float v0 = ax / s + bias_v.x;
    float v1 = ay / s + bias_v.y;
    size_t idx = (size_t)node * HC + c2;
    if (mode) {
        float2 e2 = *(const float2*)(emb + idx);
        float2 h2 = *(const float2*)(g_h1a + idx);
        float2 r;
        r.x = (e2.x + h2.x + v0) * (1.f / 3.f);
        r.y = (e2.y + h2.y + v1) * (1.f / 3.f);
        *(float2*)(outFinal + idx) = r;
    } else {
        *(float2*)(g_h1 + idx) = make_float2(v0, v1);
    }
}

// -------- BatchNorm (training-style stats) + ELU --------
__global__ __launch_bounds__(128) void bn_stats(int n) {
    int c = threadIdx.x;
    float s = 0.f, q = 0.f;
    for (int r = blockIdx.x; r < n; r += gridDim.x) {
        float v = g_h1[(size_t)r * HC + c];
        s += v; q += v * v;
    }
    atomicAdd(&g_bnsum[c], (double)s);
    atomicAdd(&g_bnsq[c], (double)q);
}

// mu/inv computed inline from the double sums (no separate bn_fin launch).
// float4 path: 4 consecutive channels per thread.
__global__ void bn_apply(const float* __restrict__ gamma, const float* __restrict__ beta, int n) {
    int idx4 = blockIdx.x * blockDim.x + threadIdx.x;     // vec4 index
    if (idx4 >= n * (HC / 4)) return;
    int c4 = (idx4 & (HC / 4 - 1)) * 4;                   // first channel of group
    double inv_n = 1.0 / n;
    float4 v = *(const float4*)&g_h1[(size_t)idx4 * 4];
    float r[4] = {v.x, v.y, v.z, v.w};
    #pragma unroll
    for (int j = 0; j < 4; j++) {
        int c = c4 + j;
        double mu = g_bnsum[c] * inv_n;
        double var = g_bnsq[c] * inv_n - mu * mu;
        float inv = rsqrtf((float)var + BN_EPS);
        float t = fmaf(__ldg(gamma + c) * (r[j] - (float)mu), inv, __ldg(beta + c));
        r[j] = (t > 0.f) ? t : expm1f(t);
    }
    *(float4*)&g_h1a[(size_t)idx4 * 4] = make_float4(r[0], r[1], r[2], r[3]);
}

// ---------------- launch ----------------
extern "C" void kernel_launch(void* const* d_in, const int* in_sizes, int n_in,
                              void* d_out, int out_size) {
    const float* emb   = (const float*)d_in[0];
    const int*   ei    = (const int*)d_in[1];   // int32 or int64 (detected)
    const float* ew    = (const float*)d_in[2];
    const float* Wl1   = (const float*)d_in[3];
    const float* bl1   = (const float*)d_in[4];
    const float* Wr1   = (const float*)d_in[5];
    const float* br1   = (const float*)d_in[6];
    const float* We1   = (const float*)d_in[7];
    const float* att1  = (const float*)d_in[8];
    const float* bias1 = (const float*)d_in[9];
    const float* gamma1= (const float*)d_in[10];
    const float* beta1 = (const float*)d_in[11];
    const float* Wl2   = (const float*)d_in[12];
    const float* bl2   = (const float*)d_in[13];
    const float* Wr2   = (const float*)d_in[14];
    const float* br2   = (const float*)d_in[15];
    const float* We2   = (const float*)d_in[16];
    const float* att2  = (const float*)d_in[17];
    const float* bias2 = (const float*)d_in[18];
    float* out = (float*)d_out;

    const int n = in_sizes[0] / HC;   // 50000
    const int E = in_sizes[2];        // 800000

    dim3 ggrid((n + 127) / 128, 1, 2);

    // preprocessing + layer-1 GEMM (sgemm1 hoisted to slot 4 -> ncu profile target)
    zero_detect_kernel<<<(NN + 255) / 256, 256>>>(ei);
    deg_kernel<<<(E + 255) / 256, 256>>>(ei, ew, E);
    scan_part<<<NB_SCAN, 256>>>(n);
    sgemm_dual<<<ggrid, 256>>>(emb, Wl1, bl1, Wr1, br1, n, 0);   // 4th launch
    scan_mid<<<1, 256>>>(NB_SCAN, E + n);
    scan_final<<<NB_SCAN, 256>>>(n);
    csr_fill<<<(E + 255) / 256, 256>>>(ei, ew, E);
    self_fill<<<(n + 255) / 256, 256>>>(n);

    // layer 1 aggregation + BN/ELU
    gat_agg<<<(n + 1) / 2, 128>>>(We1, att1, bias1, nullptr, nullptr, 0, n);
    bn_stats<<<512, 128>>>(n);
    bn_apply<<<(n * (HC / 4) + 255) / 256, 256>>>(gamma1, beta1, n);

    // layer 2 (+ fused final combine)
    sgemm_dual<<<ggrid, 256>>>(nullptr, Wl2, bl2, Wr2, br2, n, 1);
    gat_agg<<<(n + 1) / 2, 128>>>(We2, att2, bias2, emb, out, 1, n);
}

// round 16
// speedup vs baseline: 1.4391x; 1.1084x over previous
#include <cuda_runtime.h>
#include <math.h>

// ---------------- problem constants ----------------
#define NN 50000
#define EE 800000
#define HC 128          // HEADS * C_OUT
#define NSLOT (EE + NN) // edges + self loops
#define NEG_SLOPE 0.2f
#define BN_EPS 1e-5f
#define NB_SCAN ((NN + 255) / 256)   // 196
#define LOG2E 1.44269504088896f

// ---------------- device-global scratch (no allocs allowed) ----------------
__device__ int    g_is64;
__device__ int    g_deg[NN];
__device__ int    g_cursor[NN];
__device__ float  g_wsum[NN];
__device__ int    g_rowstart[NN + 1];
__device__ int    g_part[256];
__device__ int    g_csrc[NSLOT];
__device__ float  g_cw[NSLOT];
__device__ float  g_xl[NN * HC];
__device__ float  g_xr[NN * HC];
__device__ float  g_h1[NN * HC];    // raw GAT1 output
__device__ float  g_h1a[NN * HC];   // after BN + ELU
__device__ double g_bnsum[HC], g_bnsq[HC];

// ---------------- f32x2 packed-FMA helpers (sm_100+) ----------------
__device__ __forceinline__ void ffma2(unsigned long long& d,
                                      unsigned long long a,
                                      unsigned long long b) {
    asm("fma.rn.f32x2 %0, %1, %2, %0;" : "+l"(d) : "l"(a), "l"(b));
}
__device__ __forceinline__ unsigned long long pack_dup(float x) {
    unsigned long long r;
    unsigned int u = __float_as_uint(x);
    asm("mov.b64 %0, {%1, %1};" : "=l"(r) : "r"(u));
    return r;
}
__device__ __forceinline__ void unpack2(unsigned long long v, float& lo, float& hi) {
    unsigned int a, b;
    asm("mov.b64 {%0, %1}, %2;" : "=r"(a), "=r"(b) : "l"(v));
    lo = __uint_as_float(a); hi = __uint_as_float(b);
}

// ---------------- helpers ----------------
// edge_index may be int64 (reference dtype) or int32 (JAX x64-off downcast).
// int64 little-endian with values < 2^31 -> every odd 32-bit word is zero.
__device__ __forceinline__ void load_edge(const int* __restrict__ ei, int e, int E,
                                          int& s, int& d) {
    if (g_is64) { s = ei[2 * e]; d = ei[2 * (E + e)]; }
    else        { s = ei[e];     d = ei[E + e]; }
}

// zero scratch + detect int64-vs-int32 layout (fused; one launch)
__global__ void zero_detect_kernel(const int* __restrict__ ei) {
    int i = blockIdx.x * blockDim.x + threadIdx.x;
    if (i < NN) { g_deg[i] = 0; g_wsum[i] = 0.f; g_cursor[i] = 0; }
    if (i < HC) { g_bnsum[i] = 0.0; g_bnsq[i] = 0.0; }
    if (blockIdx.x == 0 && threadIdx.x == 0) {
        int z = 0;
        #pragma unroll
        for (int j = 1; j < 64; j += 2) z |= ei[j];
        g_is64 = (z == 0) ? 1 : 0;
    }
}

__global__ void deg_kernel(const int* __restrict__ ei, const float* __restrict__ ew, int E) {
    int e = blockIdx.x * blockDim.x + threadIdx.x;
    if (e >= E) return;
    int s, d; load_edge(ei, e, E, s, d);
    (void)s;
    atomicAdd(&g_deg[d], 1);
    atomicAdd(&g_wsum[d], ew[e]);
}

// -------- 3-kernel exclusive scan over counts = deg[i] + 1 --------
__global__ void scan_part(int n) {
    __shared__ int sm[256];
    int tid = threadIdx.x;
    int i = blockIdx.x * 256 + tid;
    int v = (i < n) ? (g_deg[i] + 1) : 0;
    sm[tid] = v; __syncthreads();
    for (int off = 128; off > 0; off >>= 1) {
        if (tid < off) sm[tid] += sm[tid + off];
        __syncthreads();
    }
    if (tid == 0) g_part[blockIdx.x] = sm[0];
}

__global__ void scan_mid(int nb, int total) {
    __shared__ int sm[256];
    int tid = threadIdx.x;
    int v = (tid < nb) ? g_part[tid] : 0;
    sm[tid] = v; __syncthreads();
    for (int off = 1; off < 256; off <<= 1) {
        int t = (tid >= off) ? sm[tid - off] : 0;
        __syncthreads();
        sm[tid] += t;
        __syncthreads();
    }
    if (tid < nb) g_part[tid] = sm[tid] - v;   // exclusive
    if (tid == 0) g_rowstart[NN] = total;
}

__global__ void scan_final(int n) {
    __shared__ int sm[256];
    int tid = threadIdx.x;
    int i = blockIdx.x * 256 + tid;
    int v = (i < n) ? (g_deg[i] + 1) : 0;
    sm[tid] = v; __syncthreads();
    for (int off = 1; off < 256; off <<= 1) {
        int t = (tid >= off) ? sm[tid - off] : 0;
        __syncthreads();
        sm[tid] += t;
        __syncthreads();
    }
    if (i < n) g_rowstart[i] = g_part[blockIdx.x] + sm[tid] - v;   // exclusive
}

__global__ void csr_fill(const int* __restrict__ ei, const float* __restrict__ ew, int E) {
    int e = blockIdx.x * blockDim.x + threadIdx.x;
    if (e >= E) return;
    int s, d; load_edge(ei, e, E, s, d);
    int pos = atomicAdd(&g_cursor[d], 1);
    int slot = g_rowstart[d] + pos;
    g_csrc[slot] = s;
    g_cw[slot]   = ew[e];
}

// self loop fill; loop weight = mean incoming weight (0 if no in-edges)
__global__ void self_fill(int n) {
    int i = blockIdx.x * blockDim.x + threadIdx.x;
    if (i >= n) return;
    int slot = g_rowstart[i + 1] - 1;  // last slot of node i's segment
    g_csrc[slot] = i;
    g_cw[slot]   = g_wsum[i] / fmaxf((float)g_deg[i], 1.f);
}

// -------- SGEMM: O[M,128] = A[M,128] @ W[128,128] + b, dual-W via gridDim.z --------
// BM=BN=128, BK=8, 8x8 microtiles via packed fma.rn.f32x2, 256 threads.
// Double-buffered smem (one __syncthreads per K-tile). __launch_bounds__(256,2)
// caps registers at 128 so TWO blocks fit per SM: R13 measured the double-buffer
// version at 130 regs -> 1 block/SM (occ 12.4%) -> 111.4us, a regression vs the
// 126-reg single-buffer (87.7us). Forcing <=128 regs (cost: <=2 spilled values)
// restores 2 blocks/SM while keeping the reduced-sync pipeline.
__global__ __launch_bounds__(256, 2) void sgemm_dual(
    const float* __restrict__ Aext,
    const float* __restrict__ W0, const float* __restrict__ b0,
    const float* __restrict__ W1, const float* __restrict__ b1,
    int M, int useH1a)
{
    const float* __restrict__ A    = useH1a ? g_h1a : Aext;
    const float* __restrict__ W    = blockIdx.z ? W1 : W0;
    const float* __restrict__ bias = blockIdx.z ? b1 : b0;
    float* __restrict__ O          = blockIdx.z ? g_xr : g_xl;

    __shared__ float As[2][8][128];  // [stage][k][row]
    __shared__ float Bs[2][8][128];  // [stage][k][col]

    int tid = threadIdx.x;
    int row0 = blockIdx.x * 128;
    int ty = tid / 16, tx = tid % 16;
    int c0 = tx * 4;          // first 4-col block
    int c1 = 64 + tx * 4;     // second 4-col block

    int a_r = tid >> 1;            // 0..127
    int a_c = (tid & 1) * 4;       // 0 or 4
    int b_r = tid >> 5;            // 0..7
    int b_c = (tid & 31) * 4;      // 0..124
    bool a_ok = (row0 + a_r) < M;
    const float* Aptr = A + (size_t)(row0 + a_r) * HC + a_c;
    const float* Wptr = W + b_r * 128 + b_c;

    // 8 rows x 4 column-pairs of packed f32x2 accumulators (= 8x8 floats)
    unsigned long long acc2[8][4];
    #pragma unroll
    for (int i = 0; i < 8; i++)
        #pragma unroll
        for (int j = 0; j < 4; j++) acc2[i][j] = 0ULL;

    // prologue: load + store K-tile 0 into stage 0
    {
        float4 av0 = a_ok ? *(const float4*)(Aptr) : make_float4(0.f, 0.f, 0.f, 0.f);
        float4 bv0 = *(const float4*)(Wptr);
        As[0][a_c + 0][a_r] = av0.x; As[0][a_c + 1][a_r] = av0.y;
        As[0][a_c + 2][a_r] = av0.z; As[0][a_c + 3][a_r] = av0.w;
        *(float4*)&Bs[0][b_r][b_c] = bv0;
    }
    __syncthreads();

    int p = 0;
    for (int k0 = 0; k0 < 128; k0 += 8) {
        float4 av, bv;
        bool more = (k0 + 8 < 128);
        if (more) {    // prefetch next tile from global; latency hidden by compute
            av = a_ok ? *(const float4*)(Aptr + k0 + 8) : make_float4(0.f, 0.f, 0.f, 0.f);
            bv = *(const float4*)(Wptr + (k0 + 8) * 128);
        }
        #pragma unroll
        for (int k = 0; k < 8; k++) {
            float4 ra0 = *(const float4*)&As[p][k][ty * 8];
            float4 ra1 = *(const float4*)&As[p][k][ty * 8 + 4];
            double2 rb0 = *(const double2*)&Bs[p][k][c0];
            double2 rb1 = *(const double2*)&Bs[p][k][c1];
            unsigned long long b2[4];
            b2[0] = __double_as_longlong(rb0.x);
            b2[1] = __double_as_longlong(rb0.y);
            b2[2] = __double_as_longlong(rb1.x);
            b2[3] = __double_as_longlong(rb1.y);
            float ras[8] = {ra0.x, ra0.y, ra0.z, ra0.w, ra1.x, ra1.y, ra1.z, ra1.w};
            #pragma unroll
            for (int i = 0; i < 8; i++) {
                unsigned long long a2 = pack_dup(ras[i]);
                #pragma unroll
                for (int j = 0; j < 4; j++)
                    ffma2(acc2[i][j], a2, b2[j]);
            }
        }
        if (more) {    // store into the idle stage; nobody reads it until after sync
            int q = p ^ 1;
            As[q][a_c + 0][a_r] = av.x; As[q][a_c + 1][a_r] = av.y;
            As[q][a_c + 2][a_r] = av.z; As[q][a_c + 3][a_r] = av.w;
            *(float4*)&Bs[q][b_r][b_c] = bv;
            __syncthreads();
            p = q;
        }
    }

    #pragma unroll
    for (int i = 0; i < 8; i++) {
        int r = row0 + ty * 8 + i;
        if (r < M) {
            float o[8];
            #pragma unroll
            for (int j = 0; j < 2; j++) {       // block c0
                float lo, hi;
                unpack2(acc2[i][j], lo, hi);
                o[2 * j]     = lo + __ldg(bias + c0 + 2 * j);
                o[2 * j + 1] = hi + __ldg(bias + c0 + 2 * j + 1);
            }
            #pragma unroll
            for (int j = 2; j < 4; j++) {       // block c1
                float lo, hi;
                unpack2(acc2[i][j], lo, hi);
                o[2 * j]     = lo + __ldg(bias + c1 + 2 * (j - 2));
                o[2 * j + 1] = hi + __ldg(bias + c1 + 2 * (j - 2) + 1);
            }
            *(float4*)(O + (size_t)r * HC + c0) = make_float4(o[0], o[1], o[2], o[3]);
            *(float4*)(O + (size_t)r * HC + c1) = make_float4(o[4], o[5], o[6], o[7]);
        }
    }
}

// -------- GATv2 aggregation: 2 channels per thread (float2) --------
// Warp covers 64 channels = 2 heads (16 lanes x 2ch per head). Head logit
// reduce = 4 shfl levels (xor 8/4/2/1 stays inside each 16-lane group).
// 2 nodes per 128-thread block. (R13: this shape measured ~-99us vs scalar.)
__global__ __launch_bounds__(128) void gat_agg(
    const float* __restrict__ We, const float* __restrict__ att,
    const float* __restrict__ bias,
    const float* __restrict__ emb, float* __restrict__ outFinal,
    int mode, int n)
{
    int node = blockIdx.x * 2 + (threadIdx.x >> 6);
    if (node >= n) return;
    int c2 = (threadIdx.x & 63) * 2;       // first of this thread's 2 channels

    float2 att_v = *(const float2*)(att + c2);
    att_v.x *= LOG2E; att_v.y *= LOG2E;    // base-2 softmax
    float2 we_v = *(const float2*)(We + c2);
    float2 xr_v = *(const float2*)(g_xr + (size_t)node * HC + c2);
    int start = g_rowstart[node], end = g_rowstart[node + 1];

    float m = -INFINITY, s = 0.f;
    float ax = 0.f, ay = 0.f;
    for (int i = start; i < end; ++i) {
        int   src = g_csrc[i];
        float w   = g_cw[i];
        float2 xl = *(const float2*)(g_xl + (size_t)src * HC + c2);
        float t0 = fmaf(w, we_v.x, xl.x + xr_v.x); t0 = fmaxf(t0, NEG_SLOPE * t0);
        float t1 = fmaf(w, we_v.y, xl.y + xr_v.y); t1 = fmaxf(t1, NEG_SLOPE * t1);
        float l = fmaf(att_v.x, t0, att_v.y * t1);
        l += __shfl_xor_sync(0xffffffffu, l, 8);
        l += __shfl_xor_sync(0xffffffffu, l, 4);
        l += __shfl_xor_sync(0xffffffffu, l, 2);
        l += __shfl_xor_sync(0xffffffffu, l, 1);
        float nm = fmaxf(m, l);
        float sc = exp2f(m - nm);   // first iter: exp2(-inf) = 0
        float p  = exp2f(l - nm);
        s  = fmaf(s, sc, p);
        ax = fmaf(ax, sc, p * xl.x);
        ay = fmaf(ay, sc, p * xl.y);
        m = nm;
    }
    float2 bias_v = *(const float2*)(bias + c2);
    float v0 = ax / s + bias_v.x;
    float v1 = ay / s + bias_v.y;
    size_t idx = (size_t)node * HC + c2;
    if (mode) {
        float2 e2 = *(const float2*)(emb + idx);
        float2 h2 = *(const float2*)(g_h1a + idx);
        float2 r;
        r.x = (e2.x + h2.x + v0) * (1.f / 3.f);
        r.y = (e2.y + h2.y + v1) * (1.f / 3.f);
        *(float2*)(outFinal + idx) = r;
    } else {
        *(float2*)(g_h1 + idx) = make_float2(v0, v1);
    }
}

// -------- BatchNorm (training-style stats) + ELU --------
__global__ __launch_bounds__(128) void bn_stats(int n) {
    int c = threadIdx.x;
    float s = 0.f, q = 0.f;
    for (int r = blockIdx.x; r < n; r += gridDim.x) {
        float v = g_h1[(size_t)r * HC + c];
        s += v; q += v * v;
    }
    atomicAdd(&g_bnsum[c], (double)s);
    atomicAdd(&g_bnsq[c], (double)q);
}

// mu/inv computed inline from the double sums (no separate bn_fin launch).
// float4 path: 4 consecutive channels per thread.
__global__ void bn_apply(const float* __restrict__ gamma, const float* __restrict__ beta, int n) {
    int idx4 = blockIdx.x * blockDim.x + threadIdx.x;     // vec4 index
    if (idx4 >= n * (HC / 4)) return;
    int c4 = (idx4 & (HC / 4 - 1)) * 4;                   // first channel of group
    double inv_n = 1.0 / n;
    float4 v = *(const float4*)&g_h1[(size_t)idx4 * 4];
    float r[4] = {v.x, v.y, v.z, v.w};
    #pragma unroll
    for (int j = 0; j < 4; j++) {
        int c = c4 + j;
        double mu = g_bnsum[c] * inv_n;
        double var = g_bnsq[c] * inv_n - mu * mu;
        float inv = rsqrtf((float)var + BN_EPS);
        float t = fmaf(__ldg(gamma + c) * (r[j] - (float)mu), inv, __ldg(beta + c));
        r[j] = (t > 0.f) ? t : expm1f(t);
    }
    *(float4*)&g_h1a[(size_t)idx4 * 4] = make_float4(r[0], r[1], r[2], r[3]);
}

// ---------------- launch ----------------
extern "C" void kernel_launch(void* const* d_in, const int* in_sizes, int n_in,
                              void* d_out, int out_size) {
    const float* emb   = (const float*)d_in[0];
    const int*   ei    = (const int*)d_in[1];   // int32 or int64 (detected)
    const float* ew    = (const float*)d_in[2];
    const float* Wl1   = (const float*)d_in[3];
    const float* bl1   = (const float*)d_in[4];
    const float* Wr1   = (const float*)d_in[5];
    const float* br1   = (const float*)d_in[6];
    const float* We1   = (const float*)d_in[7];
    const float* att1  = (const float*)d_in[8];
    const float* bias1 = (const float*)d_in[9];
    const float* gamma1= (const float*)d_in[10];
    const float* beta1 = (const float*)d_in[11];
    const float* Wl2   = (const float*)d_in[12];
    const float* bl2   = (const float*)d_in[13];
    const float* Wr2   = (const float*)d_in[14];
    const float* br2   = (const float*)d_in[15];
    const float* We2   = (const float*)d_in[16];
    const float* att2  = (const float*)d_in[17];
    const float* bias2 = (const float*)d_in[18];
    float* out = (float*)d_out;

    const int n = in_sizes[0] / HC;   // 50000
    const int E = in_sizes[2];        // 800000

    dim3 ggrid((n + 127) / 128, 1, 2);

    // preprocessing + layer-1 GEMM (sgemm1 hoisted to slot 4 -> ncu profile target)
    zero_detect_kernel<<<(NN + 255) / 256, 256>>>(ei);
    deg_kernel<<<(E + 255) / 256, 256>>>(ei, ew, E);
    scan_part<<<NB_SCAN, 256>>>(n);
    sgemm_dual<<<ggrid, 256>>>(emb, Wl1, bl1, Wr1, br1, n, 0);   // 4th launch
    scan_mid<<<1, 256>>>(NB_SCAN, E + n);
    scan_final<<<NB_SCAN, 256>>>(n);
    csr_fill<<<(E + 255) / 256, 256>>>(ei, ew, E);
    self_fill<<<(n + 255) / 256, 256>>>(n);

    // layer 1 aggregation + BN/ELU
    gat_agg<<<(n + 1) / 2, 128>>>(We1, att1, bias1, nullptr, nullptr, 0, n);
    bn_stats<<<512, 128>>>(n);
    bn_apply<<<(n * (HC / 4) + 255) / 256, 256>>>(gamma1, beta1, n);

    // layer 2 (+ fused final combine)
    sgemm_dual<<<ggrid, 256>>>(nullptr, Wl2, bl2, Wr2, br2, n, 1);
    gat_agg<<<(n + 1) / 2, 128>>>(We2, att2, bias2, emb, out, 1, n);
}